// round 12
// baseline (speedup 1.0000x reference)
#include <cuda_runtime.h>
#include <cuda_bf16.h>
#include <math.h>
#include <stdint.h>

// Sigma_out[b][i][l] = p_i * p_l * ( S[i][l] - q[i] - r[l] + s )
//   p = softmax(mu[b]) ; q = S p ; r = p^T S ; s = p^T S p
//
// r11 winner + deeper register retention:
//   - one CTA per batch, 256 threads, 2 CTAs/SM (full register budget)
//   - PF=28 Sigma values prefetched before the softmax AND retained in
//     registers to the end (output pass reads them instead of smem)
//   - r fused into staging (register accumulation, fixed column per thread)
//   - 16B-block swizzle: (i,k) stored at i*128 + 4*((k>>2)^(i&31)) + (k&3)
//       * staging STS scalar: banks 4*perm8 + (k&3) -> conflict-free
//       * q-pass: LDS.128 (16 float4 per thread) + float4 psh loads
//       * output LDS scalar: same conflict-free pattern
//   - global accesses stay scalar 32-bit (vector-global faults on this harness)

#define C 128
#define THREADS 256
#define EPT 64
#define PF 28

__global__ __launch_bounds__(THREADS, 2) void softmax_sigma_kernel(
    const float* __restrict__ mu,       // [B, C]
    const float* __restrict__ Sigma,    // [B, C, C]
    float* __restrict__ mu_out,         // [B, C]
    float* __restrict__ sig_out)        // [B, C, C]
{
    const int b  = blockIdx.x;
    const int t  = threadIdx.x;
    const int k  = t & (C - 1);         // fixed column for this thread
    const int c  = t >> 7;              // 0 or 1
    const int kb = k >> 2;              // fixed 16B block of column
    const int ko = k & 3;               // offset within block

    extern __shared__ __align__(16) float sm[];
    float* Ssm   = sm;                  // 16384, block-swizzled
    float* psh   = sm + C * C;          // 128
    float* pq    = psh + C;             // 128
    float* rtmp  = pq + C;              // 256
    float* qpart = rtmp + 2 * C;        // 256
    float* red   = qpart + 2 * C;       // 16

    const float* g = Sigma + (size_t)b * (C * C) + t;

    // ---- deep prefetch, retained in registers through the whole kernel
    float pfv[PF];
    #pragma unroll
    for (int j = 0; j < PF; ++j) pfv[j] = g[THREADS * j];

    // ---- softmax over mu[b]
    float x = (t < C) ? mu[b * C + t] : -INFINITY;
    float v = x;
    #pragma unroll
    for (int o = 16; o > 0; o >>= 1)
        v = fmaxf(v, __shfl_xor_sync(0xffffffffu, v, o));
    if (t < C && (t & 31) == 0) red[t >> 5] = v;
    __syncthreads();
    float m = fmaxf(fmaxf(red[0], red[1]), fmaxf(red[2], red[3]));
    float e = (t < C) ? expf(x - m) : 0.0f;
    v = e;
    #pragma unroll
    for (int o = 16; o > 0; o >>= 1)
        v += __shfl_xor_sync(0xffffffffu, v, o);
    if (t < C && (t & 31) == 0) red[8 + (t >> 5)] = v;
    __syncthreads();
    float denom = red[8] + red[9] + red[10] + red[11];
    if (t < C) {
        float pt = e / denom;
        psh[t] = pt;
        mu_out[b * C + t] = pt;
    }
    __syncthreads();

    // ---- staging + fused r accumulation (rows i = c, c+2, ...)
    {
        float racc = 0.0f;
        int i = c;
        #pragma unroll
        for (int j = 0; j < EPT; ++j) {
            float val = (j < PF) ? pfv[j] : g[THREADS * j];
            Ssm[i * C + (((kb ^ (i & 31)) << 2) | ko)] = val;
            racc = fmaf(val, psh[i], racc);
            i += 2;
        }
        rtmp[t] = racc;   // r[k] = rtmp[k] + rtmp[k+128]
    }
    __syncthreads();

    // ---- q pass, vectorized: thread t -> row iq = t&127, half c
    {
        const int iq = k;
        const int sw = iq & 31;
        const float4* row4 = reinterpret_cast<const float4*>(Ssm + iq * C);
        const float4* p4   = reinterpret_cast<const float4*>(psh);
        float acc = 0.0f;
        #pragma unroll
        for (int bb = 0; bb < 16; ++bb) {
            const int blk = 16 * c + bb;           // warp-uniform
            float4 vv = row4[blk ^ sw];
            float4 pp = p4[blk];
            acc = fmaf(vv.x, pp.x, acc);
            acc = fmaf(vv.y, pp.y, acc);
            acc = fmaf(vv.z, pp.z, acc);
            acc = fmaf(vv.w, pp.w, acc);
        }
        qpart[t] = acc;   // q[i] = qpart[i] + qpart[i+128]
    }
    __syncthreads();

    // ---- s = p . q ; pq[i] = p_i*(q_i - s)
    float qi = (t < C) ? (qpart[t] + qpart[t + C]) : 0.0f;
    float sv = (t < C) ? psh[t] * qi : 0.0f;
    #pragma unroll
    for (int o = 16; o > 0; o >>= 1)
        sv += __shfl_xor_sync(0xffffffffu, sv, o);
    if (t < C && (t & 31) == 0) red[t >> 5] = sv;
    __syncthreads();
    const float s = red[0] + red[1] + red[2] + red[3];
    if (t < C) pq[t] = psh[t] * (qi - s);
    __syncthreads();

    // ---- output: out[i][k] = p_k * ( p_i*(S[i][k] - r_k) - pq[i] )
    //      first PF values come straight from registers (no smem read)
    {
        const float pk = psh[k];
        const float rk = rtmp[k] + rtmp[k + C];
        float* o = sig_out + (size_t)b * (C * C) + t;
        int i = c;
        #pragma unroll
        for (int j = 0; j < EPT; ++j) {
            float val = (j < PF) ? pfv[j]
                                 : Ssm[i * C + (((kb ^ (i & 31)) << 2) | ko)];
            o[THREADS * j] = pk * (psh[i] * (val - rk) - pq[i]);
            i += 2;
        }
    }
}

extern "C" void kernel_launch(void* const* d_in, const int* in_sizes, int n_in,
                              void* d_out, int out_size)
{
    // Identify inputs by size: Sigma is C times larger than mu.
    const float* in0 = (const float*)d_in[0];
    const float* in1 = (const float*)d_in[1];
    const float* mu;
    const float* Sigma;
    int B;
    if (in_sizes[0] <= in_sizes[1]) {
        mu = in0; Sigma = in1; B = in_sizes[0] / C;
    } else {
        mu = in1; Sigma = in0; B = in_sizes[1] / C;
    }

    float* mu_out  = (float*)d_out;               // first B*C elements
    float* sig_out = (float*)d_out + (size_t)B * C;

    const int smem = (C * C + 2 * C + 2 * (2 * C) + 16) * sizeof(float);
    cudaFuncSetAttribute(softmax_sigma_kernel,
                         cudaFuncAttributeMaxDynamicSharedMemorySize, smem);
    softmax_sigma_kernel<<<B, THREADS, smem>>>(mu, Sigma, mu_out, sig_out);
}

// round 13
// speedup vs baseline: 1.0125x; 1.0125x over previous
#include <cuda_runtime.h>
#include <cuda_bf16.h>
#include <math.h>
#include <stdint.h>

// Sigma_out[b][i][l] = p_i * p_l * ( S[i][l] - q[i] - r[l] + s )
//   p = softmax(mu[b]) ; q = S p ; r = p^T S ; s = p^T S p
//
// r11 winner (181.0us) + __stcs on the touch-once output stream:
//   - one CTA per batch, 256 threads, 2 CTAs/SM (full register budget)
//   - PF=24 Sigma values prefetched before the softmax AND retained in
//     registers to the end (output pass reads them instead of smem)
//   - r fused into staging (register accumulation, fixed column per thread)
//   - 16B-block swizzle: (i,k) stored at i*128 + 4*((k>>2)^(i&31)) + (k&3)
//       * staging STS scalar: banks 4*perm8 + (k&3) -> conflict-free
//       * q-pass: LDS.128 (16 float4 per thread) + float4 psh loads
//       * output LDS scalar: same conflict-free pattern
//   - global accesses scalar 32-bit (vector-global faults on this harness)

#define C 128
#define THREADS 256
#define EPT 64
#define PF 24

__global__ __launch_bounds__(THREADS, 2) void softmax_sigma_kernel(
    const float* __restrict__ mu,       // [B, C]
    const float* __restrict__ Sigma,    // [B, C, C]
    float* __restrict__ mu_out,         // [B, C]
    float* __restrict__ sig_out)        // [B, C, C]
{
    const int b  = blockIdx.x;
    const int t  = threadIdx.x;
    const int k  = t & (C - 1);         // fixed column for this thread
    const int c  = t >> 7;              // 0 or 1
    const int kb = k >> 2;              // fixed 16B block of column
    const int ko = k & 3;               // offset within block

    extern __shared__ __align__(16) float sm[];
    float* Ssm   = sm;                  // 16384, block-swizzled
    float* psh   = sm + C * C;          // 128
    float* pq    = psh + C;             // 128
    float* rtmp  = pq + C;              // 256
    float* qpart = rtmp + 2 * C;        // 256
    float* red   = qpart + 2 * C;       // 16

    const float* g = Sigma + (size_t)b * (C * C) + t;

    // ---- deep prefetch, retained in registers through the whole kernel
    float pfv[PF];
    #pragma unroll
    for (int j = 0; j < PF; ++j) pfv[j] = g[THREADS * j];

    // ---- softmax over mu[b]
    float x = (t < C) ? mu[b * C + t] : -INFINITY;
    float v = x;
    #pragma unroll
    for (int o = 16; o > 0; o >>= 1)
        v = fmaxf(v, __shfl_xor_sync(0xffffffffu, v, o));
    if (t < C && (t & 31) == 0) red[t >> 5] = v;
    __syncthreads();
    float m = fmaxf(fmaxf(red[0], red[1]), fmaxf(red[2], red[3]));
    float e = (t < C) ? expf(x - m) : 0.0f;
    v = e;
    #pragma unroll
    for (int o = 16; o > 0; o >>= 1)
        v += __shfl_xor_sync(0xffffffffu, v, o);
    if (t < C && (t & 31) == 0) red[8 + (t >> 5)] = v;
    __syncthreads();
    float denom = red[8] + red[9] + red[10] + red[11];
    if (t < C) {
        float pt = e / denom;
        psh[t] = pt;
        mu_out[b * C + t] = pt;
    }
    __syncthreads();

    // ---- staging + fused r accumulation (rows i = c, c+2, ...)
    {
        float racc = 0.0f;
        int i = c;
        #pragma unroll
        for (int j = 0; j < EPT; ++j) {
            float val = (j < PF) ? pfv[j] : g[THREADS * j];
            Ssm[i * C + (((kb ^ (i & 31)) << 2) | ko)] = val;
            racc = fmaf(val, psh[i], racc);
            i += 2;
        }
        rtmp[t] = racc;   // r[k] = rtmp[k] + rtmp[k+128]
    }
    __syncthreads();

    // ---- q pass, vectorized: thread t -> row iq = t&127, half c
    {
        const int iq = k;
        const int sw = iq & 31;
        const float4* row4 = reinterpret_cast<const float4*>(Ssm + iq * C);
        const float4* p4   = reinterpret_cast<const float4*>(psh);
        float acc = 0.0f;
        #pragma unroll
        for (int bb = 0; bb < 16; ++bb) {
            const int blk = 16 * c + bb;           // warp-uniform
            float4 vv = row4[blk ^ sw];
            float4 pp = p4[blk];
            acc = fmaf(vv.x, pp.x, acc);
            acc = fmaf(vv.y, pp.y, acc);
            acc = fmaf(vv.z, pp.z, acc);
            acc = fmaf(vv.w, pp.w, acc);
        }
        qpart[t] = acc;   // q[i] = qpart[i] + qpart[i+128]
    }
    __syncthreads();

    // ---- s = p . q ; pq[i] = p_i*(q_i - s)
    float qi = (t < C) ? (qpart[t] + qpart[t + C]) : 0.0f;
    float sv = (t < C) ? psh[t] * qi : 0.0f;
    #pragma unroll
    for (int o = 16; o > 0; o >>= 1)
        sv += __shfl_xor_sync(0xffffffffu, sv, o);
    if (t < C && (t & 31) == 0) red[t >> 5] = sv;
    __syncthreads();
    const float s = red[0] + red[1] + red[2] + red[3];
    if (t < C) pq[t] = psh[t] * (qi - s);
    __syncthreads();

    // ---- output: out[i][k] = p_k * ( p_i*(S[i][k] - r_k) - pq[i] )
    //      first PF values come straight from registers; stores evict-first
    {
        const float pk = psh[k];
        const float rk = rtmp[k] + rtmp[k + C];
        float* o = sig_out + (size_t)b * (C * C) + t;
        int i = c;
        #pragma unroll
        for (int j = 0; j < EPT; ++j) {
            float val = (j < PF) ? pfv[j]
                                 : Ssm[i * C + (((kb ^ (i & 31)) << 2) | ko)];
            __stcs(o + THREADS * j, pk * (psh[i] * (val - rk) - pq[i]));
            i += 2;
        }
    }
}

extern "C" void kernel_launch(void* const* d_in, const int* in_sizes, int n_in,
                              void* d_out, int out_size)
{
    // Identify inputs by size: Sigma is C times larger than mu.
    const float* in0 = (const float*)d_in[0];
    const float* in1 = (const float*)d_in[1];
    const float* mu;
    const float* Sigma;
    int B;
    if (in_sizes[0] <= in_sizes[1]) {
        mu = in0; Sigma = in1; B = in_sizes[0] / C;
    } else {
        mu = in1; Sigma = in0; B = in_sizes[1] / C;
    }

    float* mu_out  = (float*)d_out;               // first B*C elements
    float* sig_out = (float*)d_out + (size_t)B * C;

    const int smem = (C * C + 2 * C + 2 * (2 * C) + 16) * sizeof(float);
    cudaFuncSetAttribute(softmax_sigma_kernel,
                         cudaFuncAttributeMaxDynamicSharedMemorySize, smem);
    softmax_sigma_kernel<<<B, THREADS, smem>>>(mu, Sigma, mu_out, sig_out);
}

// round 14
// speedup vs baseline: 1.0566x; 1.0436x over previous
#include <cuda_runtime.h>
#include <cuda_bf16.h>
#include <math.h>
#include <stdint.h>

// Sigma_out[b][i][l] = p_i * p_l * ( S[i][l] - q[i] - r[l] + s )
//   p = softmax(mu[b]) ; q = S p ; r = p^T S ; s = p^T S p
//
// Two-kernel version:
//   kernel 1: softmax (warp-per-row, shuffle-only) -> mu_out
//   kernel 2: r11 winner with the in-CTA softmax replaced by one load of p,
//             shrinking each CTA's serial head so the two resident CTAs/SM
//             collide less often in compute phases (DRAM fills the gaps).
// Main kernel: PF=24 register prefetch+retention, fused r in staging,
// 16B-block swizzle (staging STS / q LDS.128 / output LDS all conflict-free),
// scalar 32-bit global accesses only.

#define C 128
#define THREADS 256
#define EPT 64
#define PF 24

// ---------------- kernel 1: softmax, one warp per row --------------------
__global__ __launch_bounds__(256) void softmax_rows_kernel(
    const float* __restrict__ mu,   // [B, C]
    float* __restrict__ mu_out,     // [B, C]
    int B)
{
    const int warp = (blockIdx.x * blockDim.x + threadIdx.x) >> 5;
    const int lane = threadIdx.x & 31;
    if (warp >= B) return;

    const float* row = mu + (size_t)warp * C;
    float x0 = row[lane], x1 = row[lane + 32], x2 = row[lane + 64], x3 = row[lane + 96];

    float m = fmaxf(fmaxf(x0, x1), fmaxf(x2, x3));
    #pragma unroll
    for (int o = 16; o > 0; o >>= 1)
        m = fmaxf(m, __shfl_xor_sync(0xffffffffu, m, o));

    float e0 = expf(x0 - m), e1 = expf(x1 - m), e2 = expf(x2 - m), e3 = expf(x3 - m);
    float ssum = e0 + e1 + e2 + e3;
    #pragma unroll
    for (int o = 16; o > 0; o >>= 1)
        ssum += __shfl_xor_sync(0xffffffffu, ssum, o);
    float inv = 1.0f / ssum;

    float* orow = mu_out + (size_t)warp * C;
    orow[lane]      = e0 * inv;
    orow[lane + 32] = e1 * inv;
    orow[lane + 64] = e2 * inv;
    orow[lane + 96] = e3 * inv;
}

// ---------------- kernel 2: Sigma transform ------------------------------
__global__ __launch_bounds__(THREADS, 2) void sigma_kernel(
    const float* __restrict__ p_in,     // [B, C] = softmax(mu)
    const float* __restrict__ Sigma,    // [B, C, C]
    float* __restrict__ sig_out)        // [B, C, C]
{
    const int b  = blockIdx.x;
    const int t  = threadIdx.x;
    const int k  = t & (C - 1);
    const int c  = t >> 7;
    const int kb = k >> 2;
    const int ko = k & 3;

    extern __shared__ __align__(16) float sm[];
    float* Ssm   = sm;                  // 16384, block-swizzled
    float* psh   = sm + C * C;          // 128
    float* pq    = psh + C;             // 128
    float* rtmp  = pq + C;              // 256
    float* qpart = rtmp + 2 * C;        // 256
    float* red   = qpart + 2 * C;       // 16

    const float* g = Sigma + (size_t)b * (C * C) + t;

    // ---- deep prefetch, retained in registers through the whole kernel
    float pfv[PF];
    #pragma unroll
    for (int j = 0; j < PF; ++j) pfv[j] = g[THREADS * j];

    // ---- load p (replaces the whole in-CTA softmax)
    if (t < C) psh[t] = p_in[b * C + t];
    __syncthreads();

    // ---- staging + fused r accumulation (rows i = c, c+2, ...)
    {
        float racc = 0.0f;
        int i = c;
        #pragma unroll
        for (int j = 0; j < EPT; ++j) {
            float val = (j < PF) ? pfv[j] : g[THREADS * j];
            Ssm[i * C + (((kb ^ (i & 31)) << 2) | ko)] = val;
            racc = fmaf(val, psh[i], racc);
            i += 2;
        }
        rtmp[t] = racc;   // r[k] = rtmp[k] + rtmp[k+128]
    }
    __syncthreads();

    // ---- q pass, vectorized: thread t -> row iq = t&127, half c
    {
        const int iq = k;
        const int sw = iq & 31;
        const float4* row4 = reinterpret_cast<const float4*>(Ssm + iq * C);
        const float4* p4   = reinterpret_cast<const float4*>(psh);
        float acc = 0.0f;
        #pragma unroll
        for (int bb = 0; bb < 16; ++bb) {
            const int blk = 16 * c + bb;           // warp-uniform
            float4 vv = row4[blk ^ sw];
            float4 pp = p4[blk];
            acc = fmaf(vv.x, pp.x, acc);
            acc = fmaf(vv.y, pp.y, acc);
            acc = fmaf(vv.z, pp.z, acc);
            acc = fmaf(vv.w, pp.w, acc);
        }
        qpart[t] = acc;   // q[i] = qpart[i] + qpart[i+128]
    }
    __syncthreads();

    // ---- s = p . q ; pq[i] = p_i*(q_i - s)
    float qi = (t < C) ? (qpart[t] + qpart[t + C]) : 0.0f;
    float sv = (t < C) ? psh[t] * qi : 0.0f;
    #pragma unroll
    for (int o = 16; o > 0; o >>= 1)
        sv += __shfl_xor_sync(0xffffffffu, sv, o);
    if (t < C && (t & 31) == 0) red[t >> 5] = sv;
    __syncthreads();
    const float s = red[0] + red[1] + red[2] + red[3];
    if (t < C) pq[t] = psh[t] * (qi - s);
    __syncthreads();

    // ---- output: out[i][k] = p_k * ( p_i*(S[i][k] - r_k) - pq[i] )
    {
        const float pk = psh[k];
        const float rk = rtmp[k] + rtmp[k + C];
        float* o = sig_out + (size_t)b * (C * C) + t;
        int i = c;
        #pragma unroll
        for (int j = 0; j < EPT; ++j) {
            float val = (j < PF) ? pfv[j]
                                 : Ssm[i * C + (((kb ^ (i & 31)) << 2) | ko)];
            o[THREADS * j] = pk * (psh[i] * (val - rk) - pq[i]);
            i += 2;
        }
    }
}

extern "C" void kernel_launch(void* const* d_in, const int* in_sizes, int n_in,
                              void* d_out, int out_size)
{
    // Identify inputs by size: Sigma is C times larger than mu.
    const float* in0 = (const float*)d_in[0];
    const float* in1 = (const float*)d_in[1];
    const float* mu;
    const float* Sigma;
    int B;
    if (in_sizes[0] <= in_sizes[1]) {
        mu = in0; Sigma = in1; B = in_sizes[0] / C;
    } else {
        mu = in1; Sigma = in0; B = in_sizes[1] / C;
    }

    float* mu_out  = (float*)d_out;               // first B*C elements
    float* sig_out = (float*)d_out + (size_t)B * C;

    // kernel 1: 8 rows per 256-thread block
    int blocks1 = (B + 7) / 8;
    softmax_rows_kernel<<<blocks1, 256>>>(mu, mu_out, B);

    // kernel 2: one CTA per batch
    const int smem = (C * C + 2 * C + 2 * (2 * C) + 16) * sizeof(float);
    cudaFuncSetAttribute(sigma_kernel,
                         cudaFuncAttributeMaxDynamicSharedMemorySize, smem);
    sigma_kernel<<<B, THREADS, smem>>>(mu_out, Sigma, sig_out);
}